// round 17
// baseline (speedup 1.0000x reference)
#include <cuda_runtime.h>
#include <cuda_fp16.h>

#define NB 64
#define NL 512
#define TS 64                  // tile size
#define NT (NL / TS)           // 8 tiles
#define NUNITS 36              // 8 diag + 28 rect
#define NTHREADS 128
#define NBLOCKS (NB * NUNITS)  // 2304
#define WPB 4                  // warps per block
#define ARRIVALS (NUNITS * WPB)  // 144 warp-arrivals per batch

__device__ float g_partial[NBLOCKS * WPB];     // per-warp weighted sqrt-sums
__device__ float g_stats[NB * NT * 2 * 8];     // per (batch,tile,warp-half): 8 sums
__device__ float g_res[NB];
__device__ unsigned int g_cnt_batch[NB];       // zero-init; reset each replay
__device__ unsigned int g_cnt_final;           // zero-init; reset each replay

__device__ __forceinline__ float sqrt_approx(float x) {
    float r; asm("sqrt.approx.f32 %0, %1;" : "=f"(r) : "f"(x)); return r;
}
__device__ __forceinline__ __half2 u2h(unsigned int u) {
    __half2 h; *reinterpret_cast<unsigned int*>(&h) = u; return h;
}
__device__ __forceinline__ unsigned int h2u(__half2 h) {
    return *reinterpret_cast<unsigned int*>(&h);
}

// 64-wide tiled triangle (R16 skeleton): diag units (t,t) weight 1/2, rect
// units (tj<ti) weight 1.  2*sumsq_tri = closed - 4*sqrtsum_tri; closed form
// per-tile in EXACT fp32 from registers: sum(s1+s2)=2L*Sum(n)-2|Sum(x)|^2/field.
// Points half2-packed {input,target}: one uint4 {X2,Y2,Z2,N2}; one HFMA2 chain
// computes both tensors' s at once.
// R17: barrier-free lifecycle — ONE __syncthreads per block (stage->loop);
// stats and result partials are per-warp STGs, epilogue counts 144 warp arrivals.
__global__ void __launch_bounds__(NTHREADS) fused_kernel(
    const float* __restrict__ inp, const float* __restrict__ tgt,
    float* __restrict__ out)
{
    __shared__ uint4 sJ[TS];               // j-tile, half2-packed
    __shared__ uint4 sI[TS];               // i-tile (rect only)

    const int b   = blockIdx.x / NUNITS;
    const int u   = blockIdx.x % NUNITS;
    const int tid = threadIdx.x;
    const int w   = tid >> 5;
    const int lane = tid & 31;

    int tj, ti;
    if (u < NT) { tj = u; ti = u; }
    else {
        int rem = u - NT;
        tj = 0;
        while (rem >= NT - 1 - tj) { rem -= NT - 1 - tj; ++tj; }
        ti = tj + 1 + rem;
    }
    const bool diag = (u < NT);
    const float wt = diag ? 0.5f : 1.0f;

    // ---- staging (registers -> packed smem); stats computed pre-sync
    if (tid < 64) {
        int p = (b * NL + tj * TS + tid) * 9 + 3;
        float xi = inp[p], yi = inp[p + 1], zi = inp[p + 2];
        float xt = tgt[p], yt = tgt[p + 1], zt = tgt[p + 2];
        float ni = fmaf(xi, xi, fmaf(yi, yi, zi * zi));
        float nt = fmaf(xt, xt, fmaf(yt, yt, zt * zt));
        uint4 v;
        v.x = h2u(__floats2half2_rn(xi, xt));
        v.y = h2u(__floats2half2_rn(yi, yt));
        v.z = h2u(__floats2half2_rn(zi, zt));
        v.w = h2u(__floats2half2_rn(ni, nt));
        sJ[tid] = v;
        if (diag) {
            // fp32 per-warp stats straight from registers (no barrier needed)
            float s[8] = {xi, yi, zi, ni, xt, yt, zt, nt};
#pragma unroll
            for (int q = 0; q < 8; ++q)
#pragma unroll
                for (int off = 16; off > 0; off >>= 1)
                    s[q] += __shfl_down_sync(0xFFFFFFFFu, s[q], off);
            if (lane == 0) {
                float* dst = &g_stats[((b * NT + u) * 2 + w) * 8];
#pragma unroll
                for (int q = 0; q < 8; ++q) dst[q] = s[q];
            }
        }
    } else if (!diag) {
        int lp = tid - 64;
        int p = (b * NL + ti * TS + lp) * 9 + 3;
        float a0 = inp[p], a1 = inp[p + 1], a2 = inp[p + 2];
        float c0 = tgt[p], c1 = tgt[p + 1], c2 = tgt[p + 2];
        uint4 v;
        v.x = h2u(__floats2half2_rn(a0, c0));
        v.y = h2u(__floats2half2_rn(a1, c1));
        v.z = h2u(__floats2half2_rn(a2, c2));
        v.w = h2u(__floats2half2_rn(fmaf(a0, a0, fmaf(a1, a1, a2 * a2)),
                                    fmaf(c0, c0, fmaf(c1, c1, c2 * c2))));
        sI[lp] = v;
    }
    __syncthreads();                       // the ONLY block barrier

    // ---- j-constants: thread owns j = tid&63, prescaled by -2 (exact)
    const int lj = tid & 63;
    const uint4 jv = sJ[lj];
    const __half2 NEG2 = __floats2half2_rn(-2.0f, -2.0f);
    const __half2 Xj = __hmul2(u2h(jv.x), NEG2);
    const __half2 Yj = __hmul2(u2h(jv.y), NEG2);
    const __half2 Zj = __hmul2(u2h(jv.z), NEG2);
    const __half2 Nj = u2h(jv.w);

    const uint4* Ib = diag ? sJ : sI;
    const int i0 = (tid >> 6) * 32;

    float acc = 0.0f;
#pragma unroll 8
    for (int i = i0; i < i0 + 32; ++i) {
        const uint4 iv = Ib[i];            // ONE broadcast LDS.128, both tensors
        __half2 g = __hfma2(u2h(iv.x), Xj,
                    __hfma2(u2h(iv.y), Yj,
                    __hfma2(u2h(iv.z), Zj, u2h(iv.w))));
        __half2 s = __hadd2(g, Nj);        // {s_in, s_tg}
        float2 f = __half22float2(s);
        acc += sqrt_approx(fabsf(f.x * f.y));
    }
    acc *= wt;

    // ---- per-warp reduce + independent retirement (no post-loop barriers)
#pragma unroll
    for (int off = 16; off > 0; off >>= 1)
        acc += __shfl_down_sync(0xFFFFFFFFu, acc, off);

    if (lane == 0) {
        g_partial[blockIdx.x * WPB + w] = acc;
        __threadfence();
        unsigned int old = atomicAdd(&g_cnt_batch[b], 1u);
        if (old == ARRIVALS - 1) {
            __threadfence();               // acquire: others' partials visible
            // fixed-order sums -> deterministic
            float sq = 0.0f;
            const float* pp = &g_partial[b * NUNITS * WPB];
#pragma unroll 16
            for (int k = 0; k < ARRIVALS; ++k) sq += pp[k];
            float v[8];
#pragma unroll
            for (int q = 0; q < 8; ++q) {
                float s = 0.0f;
                const float* st = &g_stats[b * NT * 2 * 8];
#pragma unroll
                for (int t = 0; t < NT * 2; ++t) s += st[t * 8 + q];
                v[q] = s;
            }
            float c1 = 2.0f * NL * v[3] - 2.0f * (v[0]*v[0] + v[1]*v[1] + v[2]*v[2]);
            float c2 = 2.0f * NL * v[7] - 2.0f * (v[4]*v[4] + v[5]*v[5] + v[6]*v[6]);
            float total = (c1 + c2) - 4.0f * sq;   // == 2 * sumsq_tri
            float res = sqrtf(total + 1e-6f);
            res *= (1.0f / (sqrtf((float)NL * (float)(NL - 1)) * (float)NL));
            g_res[b] = res;
            g_cnt_batch[b] = 0;            // reset for next replay
            __threadfence();
            unsigned int o2 = atomicAdd(&g_cnt_final, 1u);
            if (o2 == NB - 1) {
                __threadfence();
                float s = 0.0f;
#pragma unroll
                for (int bb = 0; bb < NB; ++bb) s += g_res[bb];
                out[0] = s * (1.0f / (float)NB);
                g_cnt_final = 0;           // reset for next replay
            }
        }
    }
}

extern "C" void kernel_launch(void* const* d_in, const int* in_sizes, int n_in,
                              void* d_out, int out_size)
{
    const float* inp = (const float*)d_in[0];
    const float* tgt = (const float*)d_in[1];
    float* out = (float*)d_out;
    fused_kernel<<<NBLOCKS, NTHREADS>>>(inp, tgt, out);
}